// round 11
// baseline (speedup 1.0000x reference)
#include <cuda_runtime.h>
#include <cuda_fp16.h>
#include <cstdint>

// ---------------- problem dims (fixed) ----------------
#define BATCH   32
#define RDIM    5
#define NNODES  1024
#define DDIM    256
#define HDIM    256
#define MTOT    (BATCH * NNODES)    // 32768

// ---------------- tiling (R9-proven: TM=128, TH=64, 8 warps) -------------
#define TM      128
#define TH      64
#define SAB     528                 // A row stride bytes (264 fp16)
#define ABUF    (TM * SAB)          // 67584 per A buffer
// w0 half-K chunk: 64 h-rows x 128 K fp16, stride 272; hi + lo
#define BROW    272
#define BCHUNK  (TH * BROW)         // 17408
#define WSLOT   (2 * BCHUNK)        // 34816
#define SMA_TOTAL (2 * ABUF + 2 * WSLOT)   // 204800 (kernel A)
// relation full-K chunk: 64 h-rows x 256 K fp16, stride 528 (hi only)
#define RROW    528
#define RCHUNK  (TH * RROW)         // 33792
#define SMB_TOTAL (ABUF + 2 * RCHUNK)      // 135168 (kernel B)

#define NRS     640                 // rowsum CTAs (each: 256 adj rows)
#define NGEMM   1024                // w0 GEMM CTAs (256 m-tiles x 4 h-tiles)

// ---------------- device scratch ----------------
__device__ __align__(16) __half g_nhi[MTOT * DDIM];        // nodes fp16 hi [m][d]
__device__ __align__(16) __half g_nlo[MTOT * DDIM];        // nodes fp16 lo
__device__ __align__(16) __half g_whi[6 * HDIM * DDIM];    // [g][h][d] fp16 (g0=w0)
__device__ __align__(16) __half g_wlo[HDIM * DDIM];        // w0 fp16 lo
__device__ float g_invc[BATCH * RDIM * NNODES];            // 1/rowsum (0 -> 1)

// ---------------- helpers ----------------
__device__ __forceinline__ uint32_t smem_u32(const void* p) {
    uint32_t a;
    asm("{ .reg .u64 t; cvta.to.shared.u64 t, %1; cvt.u32.u64 %0, t; }" : "=r"(a) : "l"(p));
    return a;
}
__device__ __forceinline__ void ldm4(uint32_t* r, uint32_t addr) {
    asm volatile("ldmatrix.sync.aligned.m8n8.x4.shared.b16 {%0,%1,%2,%3}, [%4];"
                 : "=r"(r[0]), "=r"(r[1]), "=r"(r[2]), "=r"(r[3]) : "r"(addr));
}
__device__ __forceinline__ void mma16816(float* c, const uint32_t* a,
                                         uint32_t b0, uint32_t b1) {
    asm volatile("mma.sync.aligned.m16n8k16.row.col.f32.f16.f16.f32 "
                 "{%0,%1,%2,%3}, {%4,%5,%6,%7}, {%8,%9}, {%0,%1,%2,%3};"
                 : "+f"(c[0]), "+f"(c[1]), "+f"(c[2]), "+f"(c[3])
                 : "r"(a[0]), "r"(a[1]), "r"(a[2]), "r"(a[3]), "r"(b0), "r"(b1));
}
__device__ __forceinline__ void cpasync16(uint32_t dst, const void* src) {
    asm volatile("cp.async.cg.shared.global [%0], [%1], 16;" :: "r"(dst), "l"(src));
}
template<int N> __device__ __forceinline__ void cpwait() {
    asm volatile("cp.async.wait_group %0;" :: "n"(N));
}
#define CP_COMMIT() asm volatile("cp.async.commit_group;" ::: "memory")

__device__ __forceinline__ uint32_t hscale(uint32_t v, uint32_t s2) {
    __half2 r = __hmul2(*reinterpret_cast<__half2*>(&v),
                        *reinterpret_cast<__half2*>(&s2));
    return *reinterpret_cast<uint32_t*>(&r);
}

// ---------------- kernel 1: nodes -> fp16 hi/lo ----------------
__global__ void prep_nodes_kernel(const float* __restrict__ nodes) {
    int idx = blockIdx.x * blockDim.x + threadIdx.x;    // float4 index
    if (idx >= MTOT * DDIM / 4) return;
    float4 v = reinterpret_cast<const float4*>(nodes)[idx];
    __half h0 = __float2half_rn(v.x), h1 = __float2half_rn(v.y);
    __half h2 = __float2half_rn(v.z), h3 = __float2half_rn(v.w);
    __half l0 = __float2half_rn(v.x - __half2float(h0));
    __half l1 = __float2half_rn(v.y - __half2float(h1));
    __half l2 = __float2half_rn(v.z - __half2float(h2));
    __half l3 = __float2half_rn(v.w - __half2float(h3));
    __half2 hA = {h0, h1}, hB = {h2, h3}, lA = {l0, l1}, lB = {l2, l3};
    uint2 hp = make_uint2(*reinterpret_cast<uint32_t*>(&hA), *reinterpret_cast<uint32_t*>(&hB));
    uint2 lp = make_uint2(*reinterpret_cast<uint32_t*>(&lA), *reinterpret_cast<uint32_t*>(&lB));
    reinterpret_cast<uint2*>(g_nhi)[idx] = hp;
    reinterpret_cast<uint2*>(g_nlo)[idx] = lp;
}

// ---------------- kernel 2: weights -> stacked [g][h][d] fp16 ------------
__global__ void prep_w_kernel(const float* __restrict__ w0,
                              const float* __restrict__ wr) {
    int idx = blockIdx.x * blockDim.x + threadIdx.x;
    if (idx >= 6 * HDIM * DDIM) return;
    int g = idx / (HDIM * DDIM);
    int r = idx % (HDIM * DDIM);      // = h*DDIM + d
    float v = (g == 0) ? w0[r] : wr[(g - 1) * HDIM * DDIM + r];
    __half h = __float2half_rn(v);
    g_whi[idx] = h;
    if (g == 0) g_wlo[r] = __float2half_rn(v - __half2float(h));
}

// ---------------- kernel 3 (A): heterogeneous w0-GEMM + adj rowsum -------
// 1664 CTAs of 256 threads. Even blocks < 1280 -> rowsum (640 CTAs, DRAM
// streaming, no smem use). Others -> w0 GEMM (1024 CTAs = 256 m x 4 h),
// 3-pass fp16 hi/lo split, writes out. Roles interleave so every wave
// overlaps DRAM streaming with tensor work.
__global__ __launch_bounds__(256, 1) void w0_rowsum_kernel(
        const float* __restrict__ adj, float* __restrict__ out) {
    const int bx = blockIdx.x;
    const int tid  = threadIdx.x;
    const int wid  = tid >> 5;
    const int lane = tid & 31;

    if (bx < 1280 && (bx & 1) == 0) {
        // ---- rowsum role: 256 adj rows (2-row interleave for MLP) ----
        const int base = (bx >> 1) * 256 + wid * 32;
        #pragma unroll 1
        for (int r = 0; r < 32; r += 2) {
            size_t ridx = (size_t)(base + r);
            const float4* rp0 = reinterpret_cast<const float4*>(adj) + ridx * 256;
            const float4* rp1 = rp0 + 256;
            float s0 = 0.0f, s1 = 0.0f;
            #pragma unroll
            for (int i = 0; i < 8; i++) {
                float4 v0 = __ldcs(&rp0[lane + i * 32]);
                float4 v1 = __ldcs(&rp1[lane + i * 32]);
                s0 += (v0.x + v0.y) + (v0.z + v0.w);
                s1 += (v1.x + v1.y) + (v1.z + v1.w);
            }
            #pragma unroll
            for (int o = 16; o > 0; o >>= 1) {
                s0 += __shfl_xor_sync(0xffffffffu, s0, o);
                s1 += __shfl_xor_sync(0xffffffffu, s1, o);
            }
            if (lane == 0) {
                if (s0 == 0.0f) s0 = 1.0f;
                if (s1 == 0.0f) s1 = 1.0f;
                g_invc[ridx]     = 1.0f / s0;
                g_invc[ridx + 1] = 1.0f / s1;
            }
        }
        return;
    }

    // ---- w0 GEMM role ----
    const int gx = (bx < 1280) ? (bx >> 1) : (NRS + (bx - 1280));
    extern __shared__ char smem[];
    const uint32_t sb = smem_u32(smem);
    const int wm = wid >> 1;            // 0..3
    const int wh = wid & 1;             // 0..1
    const int tile_m = (gx >> 2) * TM;
    const int tile_h = (gx & 3) * TH;

    // stage A hi/lo (group 0)
    #pragma unroll
    for (int i = tid; i < TM * 32; i += 256) {
        int row = i >> 5;
        int cq  = i & 31;
        size_t src = (size_t)(tile_m + row) * DDIM + cq * 8;
        uint32_t d = sb + (uint32_t)row * SAB + cq * 16;
        cpasync16(d, &g_nhi[src]);
        cpasync16(d + ABUF, &g_nlo[src]);
    }
    CP_COMMIT();

    // stage both w0 half-K chunks (groups 1, 2)
    #pragma unroll 1
    for (int c = 0; c < 2; c++) {
        uint32_t base = sb + 2 * ABUF + (uint32_t)c * WSLOT;
        #pragma unroll
        for (int i = tid; i < TH * 16; i += 256) {
            int row = i >> 4;
            int cq  = i & 15;
            size_t src = (size_t)(tile_h + row) * DDIM + c * 128 + cq * 8;
            uint32_t d = base + (uint32_t)row * BROW + cq * 16;
            cpasync16(d, &g_whi[src]);
            cpasync16(d + BCHUNK, &g_wlo[src]);
        }
        CP_COMMIT();
    }

    const uint32_t aRow = (uint32_t)(wm * 32 + (lane & 15)) * SAB + (lane >> 4) * 16;
    const uint32_t aHi0 = sb + aRow;
    const uint32_t aHi1 = aHi0 + 16 * SAB;
    const uint32_t aLo0 = aHi0 + ABUF;
    const uint32_t aLo1 = aLo0 + 16 * SAB;
    const int n_loc  = (lane & 7) + ((lane >> 4) << 3);
    const int k_half = (lane >> 3) & 1;
    const uint32_t bOffH = (uint32_t)(wh * 32 + n_loc) * BROW + (uint32_t)k_half * 16;

    float run[2][4][4];
    #pragma unroll
    for (int mi = 0; mi < 2; mi++)
        #pragma unroll
        for (int ni = 0; ni < 4; ni++)
            #pragma unroll
            for (int q = 0; q < 4; q++) run[mi][ni][q] = 0.0f;

    #pragma unroll 1
    for (int c = 0; c < 2; c++) {
        if (c == 0) cpwait<1>(); else cpwait<0>();
        __syncthreads();

        const uint32_t aq = (uint32_t)c * 256;      // 128 K-cols * 2B
        const uint32_t bH = sb + 2 * ABUF + (uint32_t)c * WSLOT + bOffH;
        const uint32_t bL = bH + BCHUNK;
        #pragma unroll 2
        for (int kc = 0; kc < 8; kc++) {
            const uint32_t ko = (uint32_t)kc * 32;
            const uint32_t ka = aq + ko;
            uint32_t ah0[4], ah1[4], al0[4], al1[4];
            uint32_t bh0[4], bh1[4], bl0[4], bl1[4];
            ldm4(ah0, aHi0 + ka);
            ldm4(ah1, aHi1 + ka);
            ldm4(bh0, bH + ko);
            ldm4(bh1, bH + 16 * BROW + ko);
            ldm4(al0, aLo0 + ka);
            ldm4(al1, aLo1 + ka);
            ldm4(bl0, bL + ko);
            ldm4(bl1, bL + 16 * BROW + ko);
            // hi*hi
            mma16816(run[0][0], ah0, bh0[0], bh0[1]);
            mma16816(run[0][1], ah0, bh0[2], bh0[3]);
            mma16816(run[0][2], ah0, bh1[0], bh1[1]);
            mma16816(run[0][3], ah0, bh1[2], bh1[3]);
            mma16816(run[1][0], ah1, bh0[0], bh0[1]);
            mma16816(run[1][1], ah1, bh0[2], bh0[3]);
            mma16816(run[1][2], ah1, bh1[0], bh1[1]);
            mma16816(run[1][3], ah1, bh1[2], bh1[3]);
            // hi*lo
            mma16816(run[0][0], ah0, bl0[0], bl0[1]);
            mma16816(run[0][1], ah0, bl0[2], bl0[3]);
            mma16816(run[0][2], ah0, bl1[0], bl1[1]);
            mma16816(run[0][3], ah0, bl1[2], bl1[3]);
            mma16816(run[1][0], ah1, bl0[0], bl0[1]);
            mma16816(run[1][1], ah1, bl0[2], bl0[3]);
            mma16816(run[1][2], ah1, bl1[0], bl1[1]);
            mma16816(run[1][3], ah1, bl1[2], bl1[3]);
            // lo*hi
            mma16816(run[0][0], al0, bh0[0], bh0[1]);
            mma16816(run[0][1], al0, bh0[2], bh0[3]);
            mma16816(run[0][2], al0, bh1[0], bh1[1]);
            mma16816(run[0][3], al0, bh1[2], bh1[3]);
            mma16816(run[1][0], al1, bh0[0], bh0[1]);
            mma16816(run[1][1], al1, bh0[2], bh0[3]);
            mma16816(run[1][2], al1, bh1[0], bh1[1]);
            mma16816(run[1][3], al1, bh1[2], bh1[3]);
        }
    }

    // epilogue: write w0 result
    #pragma unroll
    for (int mi = 0; mi < 2; mi++) {
        int rowA = tile_m + wm * 32 + mi * 16 + (lane >> 2);
        #pragma unroll
        for (int ni = 0; ni < 4; ni++) {
            int col = tile_h + wh * 32 + ni * 8 + (lane & 3) * 2;
            *reinterpret_cast<float2*>(&out[(size_t)rowA * HDIM + col]) =
                make_float2(run[mi][ni][0], run[mi][ni][1]);
            *reinterpret_cast<float2*>(&out[(size_t)(rowA + 8) * HDIM + col]) =
                make_float2(run[mi][ni][2], run[mi][ni][3]);
        }
    }
}

// ---------------- kernel 4 (B): relation GEMM, out += --------------------
// grid (256, 4), 256 threads. A-hi staged once; 5 relation full-K chunks
// double-buffered; A fragments pre-scaled by s(g,m) in fp16 (R10-verified).
__global__ __launch_bounds__(256, 1) void rel_gemm_kernel(float* __restrict__ out) {
    extern __shared__ char smem[];
    const uint32_t sb = smem_u32(smem);
    const int tid  = threadIdx.x;
    const int wid  = tid >> 5;
    const int lane = tid & 31;
    const int wm = wid >> 1;
    const int wh = wid & 1;
    const int tile_m = blockIdx.x * TM;
    const int tile_h = blockIdx.y * TH;

    // stage A hi (group 0)
    #pragma unroll
    for (int i = tid; i < TM * 32; i += 256) {
        int row = i >> 5;
        int cq  = i & 31;
        size_t src = (size_t)(tile_m + row) * DDIM + cq * 8;
        cpasync16(sb + (uint32_t)row * SAB + cq * 16, &g_nhi[src]);
    }
    CP_COMMIT();

    auto stage_rel = [&](int slot, int rel) {
        uint32_t base = sb + ABUF + (uint32_t)slot * RCHUNK;
        #pragma unroll
        for (int i = tid; i < TH * 32; i += 256) {
            int row = i >> 5;
            int cq  = i & 31;
            size_t src = ((size_t)(rel + 1) * HDIM + tile_h + row) * DDIM + cq * 8;
            cpasync16(base + (uint32_t)row * RROW + cq * 16, &g_whi[src]);
        }
        CP_COMMIT();
    };

    stage_rel(0, 0);    // group 1

    const uint32_t aRow = (uint32_t)(wm * 32 + (lane & 15)) * SAB + (lane >> 4) * 16;
    const uint32_t aHi0 = sb + aRow;
    const uint32_t aHi1 = aHi0 + 16 * SAB;
    const int n_loc  = (lane & 7) + ((lane >> 4) << 3);
    const int k_half = (lane >> 3) & 1;
    const uint32_t bOffR = (uint32_t)(wh * 32 + n_loc) * RROW + (uint32_t)k_half * 16;

    const int r0 = tile_m + wm * 32 + (lane >> 2);

    float run[2][4][4];
    #pragma unroll
    for (int mi = 0; mi < 2; mi++)
        #pragma unroll
        for (int ni = 0; ni < 4; ni++)
            #pragma unroll
            for (int q = 0; q < 4; q++) run[mi][ni][q] = 0.0f;

    #pragma unroll 1
    for (int rel = 0; rel < RDIM; rel++) {
        if (rel + 1 < RDIM) {
            stage_rel((rel + 1) & 1, rel + 1);
            cpwait<1>();
        } else {
            cpwait<0>();
        }
        __syncthreads();

        // per-thread fp16 scales for this relation's 4 fragment rows
        uint32_t s2[4];
        #pragma unroll
        for (int j = 0; j < 4; j++) {
            int row = r0 + j * 8;
            int b = row >> 10, n = row & 1023;
            float s = g_invc[((size_t)b * RDIM + rel) * NNODES + n];
            __half2 h = __float2half2_rn(s);
            s2[j] = *reinterpret_cast<uint32_t*>(&h);
        }

        const uint32_t bB = sb + ABUF + (uint32_t)(rel & 1) * RCHUNK + bOffR;
        #pragma unroll 4
        for (int kc = 0; kc < 16; kc++) {
            const uint32_t ko = (uint32_t)kc * 32;
            uint32_t a0[4], a1[4], b0[4], b1[4];
            ldm4(a0, aHi0 + ko);
            ldm4(a1, aHi1 + ko);
            ldm4(b0, bB + ko);
            ldm4(b1, bB + 16 * RROW + ko);
            a0[0] = hscale(a0[0], s2[0]);  a0[2] = hscale(a0[2], s2[0]);
            a0[1] = hscale(a0[1], s2[1]);  a0[3] = hscale(a0[3], s2[1]);
            a1[0] = hscale(a1[0], s2[2]);  a1[2] = hscale(a1[2], s2[2]);
            a1[1] = hscale(a1[1], s2[3]);  a1[3] = hscale(a1[3], s2[3]);
            mma16816(run[0][0], a0, b0[0], b0[1]);
            mma16816(run[0][1], a0, b0[2], b0[3]);
            mma16816(run[0][2], a0, b1[0], b1[1]);
            mma16816(run[0][3], a0, b1[2], b1[3]);
            mma16816(run[1][0], a1, b0[0], b0[1]);
            mma16816(run[1][1], a1, b0[2], b0[3]);
            mma16816(run[1][2], a1, b1[0], b1[1]);
            mma16816(run[1][3], a1, b1[2], b1[3]);
        }
        __syncthreads();    // slot (rel&1) free for rel+1's prefetch... (already issued; guards rel+2)
    }

    // epilogue: out += relation sum
    #pragma unroll
    for (int mi = 0; mi < 2; mi++) {
        int rowA = tile_m + wm * 32 + mi * 16 + (lane >> 2);
        #pragma unroll
        for (int ni = 0; ni < 4; ni++) {
            int col = tile_h + wh * 32 + ni * 8 + (lane & 3) * 2;
            float2* p0 = reinterpret_cast<float2*>(&out[(size_t)rowA * HDIM + col]);
            float2* p1 = reinterpret_cast<float2*>(&out[(size_t)(rowA + 8) * HDIM + col]);
            float2 v0 = *p0, v1 = *p1;
            v0.x += run[mi][ni][0]; v0.y += run[mi][ni][1];
            v1.x += run[mi][ni][2]; v1.y += run[mi][ni][3];
            *p0 = v0; *p1 = v1;
        }
    }
}

// ---------------- launch ----------------
extern "C" void kernel_launch(void* const* d_in, const int* in_sizes, int n_in,
                              void* d_out, int out_size) {
    const float* nodes = (const float*)d_in[0];
    const float* adj   = (const float*)d_in[1];
    const float* w0    = (const float*)d_in[2];
    const float* wr    = (const float*)d_in[3];
    float* out = (float*)d_out;

    cudaFuncSetAttribute(w0_rowsum_kernel,
                         cudaFuncAttributeMaxDynamicSharedMemorySize, SMA_TOTAL);
    cudaFuncSetAttribute(rel_gemm_kernel,
                         cudaFuncAttributeMaxDynamicSharedMemorySize, SMB_TOTAL);

    prep_nodes_kernel<<<(MTOT * DDIM / 4 + 255) / 256, 256>>>(nodes);
    prep_w_kernel<<<(6 * HDIM * DDIM + 255) / 256, 256>>>(w0, wr);
    w0_rowsum_kernel<<<NRS + NGEMM, 256, SMA_TOTAL>>>(adj, out);
    rel_gemm_kernel<<<dim3(MTOT / TM, HDIM / TH), 256, SMB_TOTAL>>>(out);
}